// round 2
// baseline (speedup 1.0000x reference)
#include <cuda_runtime.h>
#include <cstdint>
#include <cstddef>

// ============================================================================
// Problem constants + scratch (no tcgen05 on this toolchain: PTX target is
// plain sm_100, so arch-accelerated tcgen05/TMEM is unavailable. Use
// mma.sync tf32 HMMA, which sm_100 supports.)
// ============================================================================

static constexpr int N_NODES = 8192;
static constexpr int D_FEAT  = 128;

__device__ __align__(128) float g_dinv[N_NODES];
__device__ __align__(128) float g_Gt[(size_t)D_FEAT * N_NODES];  // [o][k] K-major, 4 MB

// ============================================================================
// K1: deg row sums -> dinv = rsqrt(deg).  One block per row, 128 threads.
// Pure DRAM stream: 268 MB.
// ============================================================================

__global__ __launch_bounds__(128) void deg_kernel(const float* __restrict__ A) {
    __shared__ float red[4];
    const int row = blockIdx.x;
    const int t = threadIdx.x;
    const float4* a4 = reinterpret_cast<const float4*>(A + (size_t)row * N_NODES);
    float s0 = 0.f, s1 = 0.f, s2 = 0.f, s3 = 0.f;
    #pragma unroll
    for (int i = 0; i < 4; i++) {
        float4 v0 = a4[t + (4 * i + 0) * 128];
        float4 v1 = a4[t + (4 * i + 1) * 128];
        float4 v2 = a4[t + (4 * i + 2) * 128];
        float4 v3 = a4[t + (4 * i + 3) * 128];
        s0 += v0.x + v0.y + v0.z + v0.w;
        s1 += v1.x + v1.y + v1.z + v1.w;
        s2 += v2.x + v2.y + v2.z + v2.w;
        s3 += v3.x + v3.y + v3.z + v3.w;
    }
    float s = (s0 + s1) + (s2 + s3);
    #pragma unroll
    for (int off = 16; off > 0; off >>= 1)
        s += __shfl_xor_sync(0xFFFFFFFFu, s, off);
    if ((t & 31) == 0) red[t >> 5] = s;
    __syncthreads();
    if (t == 0) {
        float total = (red[0] + red[1]) + (red[2] + red[3]);
        g_dinv[row] = rsqrtf(total);
    }
}

// ============================================================================
// K2: Gt[o][k] = 1.000338 * dinv[k] * sum_d X[k][d] * W[o][d], RNA-rounded
// to tf32 (so the MMA's truncation of B is a no-op). The 1.000338 factor
// cancels the mean RZ-truncation bias of A inside the tf32 HMMA
// (E[trunc loss] = 2^-11 * ln2 for uniform mantissas; A is all-positive so
// the bias is systematic).
// ============================================================================

static constexpr int K2_ROWS = 32;
static constexpr int W_PAD   = 132;
static constexpr int K2_SMEM = (128 * W_PAD + 128) * 4;

__global__ __launch_bounds__(128) void build_gt(const float* __restrict__ X,
                                                const float* __restrict__ W) {
    extern __shared__ __align__(16) float k2sm[];
    float* Ws = k2sm;                 // [128][W_PAD]
    float* Xs = k2sm + 128 * W_PAD;   // [128]

    for (int idx = threadIdx.x; idx < 128 * 128; idx += 128) {
        int o = idx >> 7, d = idx & 127;
        Ws[o * W_PAD + d] = W[idx];
    }
    __syncthreads();

    const int k0 = blockIdx.x * K2_ROWS;
    const int o = threadIdx.x;
    const float4* Wrow = reinterpret_cast<const float4*>(Ws + o * W_PAD);

    for (int kk = 0; kk < K2_ROWS; kk++) {
        const int k = k0 + kk;
        Xs[o] = X[(size_t)k * 128 + o];
        __syncthreads();
        const float4* X4 = reinterpret_cast<const float4*>(Xs);
        float acc = 0.f;
        #pragma unroll
        for (int q = 0; q < 32; q++) {
            float4 w = Wrow[q];
            float4 x = X4[q];
            acc += w.x * x.x + w.y * x.y + w.z * x.z + w.w * x.w;
        }
        float v = acc * g_dinv[k] * 1.000338f;
        uint32_t tv;
        asm("cvt.rna.tf32.f32 %0, %1;" : "=r"(tv) : "f"(v));
        g_Gt[(size_t)o * N_NODES + k] = __uint_as_float(tv);
        __syncthreads();
    }
}

// ============================================================================
// K3: tf32 mma.sync GEMM + fused epilogue.
//   out[m][o] = relu(dinv[m] * sum_k A[m][k] * Gt[o][k])
// CTA tile 64x128, K chunk 32, 6-stage cp.async pipeline, 8 warps (warp tile
// 32x32 via m16n8k8). Smem rows padded to 36 floats: 36 mod 32 = 4, so the
// fragment-load address pattern 36*(lane/4)+lane%4 maps bank = lane ->
// conflict-free.
// ============================================================================

static constexpr int TILE_M = 64;
static constexpr int TILE_N = 128;
static constexpr int KC     = 32;
static constexpr int STAGES = 6;
static constexpr int ITERS  = N_NODES / KC;                 // 256
static constexpr int ROWPAD = 36;                           // floats (144 B)
static constexpr uint32_t A_STAGE_B = TILE_M * ROWPAD * 4;  // 9216
static constexpr uint32_t B_STAGE_B = TILE_N * ROWPAD * 4;  // 18432
static constexpr uint32_t STAGE_B   = A_STAGE_B + B_STAGE_B;  // 27648
static constexpr uint32_t GEMM_SMEM = STAGES * STAGE_B;       // 165888
static constexpr int STAGE_F  = STAGE_B / 4;                  // 6912 floats
static constexpr int A_STAGE_F = A_STAGE_B / 4;               // 2304 floats
static constexpr int CHUNKS_A = TILE_M * KC * 4 / 16;         // 512
static constexpr int CHUNKS   = CHUNKS_A + TILE_N * KC * 4 / 16;  // 1536
static constexpr int CPT      = CHUNKS / 256;                 // 6 per thread

__device__ __forceinline__ uint32_t smem_to_u32(const void* p) {
    uint32_t a;
    asm("{ .reg .u64 t; cvta.to.shared.u64 t, %1; cvt.u32.u64 %0, t; }"
        : "=r"(a) : "l"(p));
    return a;
}

__device__ __forceinline__ void mma_tf32(float d[4], const uint32_t a[4],
                                         const uint32_t b[2]) {
    asm volatile(
        "mma.sync.aligned.m16n8k8.row.col.f32.tf32.tf32.f32 "
        "{%0,%1,%2,%3}, {%4,%5,%6,%7}, {%8,%9}, {%0,%1,%2,%3};"
        : "+f"(d[0]), "+f"(d[1]), "+f"(d[2]), "+f"(d[3])
        : "r"(a[0]), "r"(a[1]), "r"(a[2]), "r"(a[3]), "r"(b[0]), "r"(b[1]));
}

__global__ __launch_bounds__(256, 1) void gcn_gemm(const float* __restrict__ A,
                                                   float* __restrict__ out) {
    extern __shared__ __align__(16) float smem_f[];
    const int tid = threadIdx.x;
    const int lane = tid & 31;
    const int wid = tid >> 5;
    const int warp_m = wid & 1;        // 2 x 32 rows
    const int warp_n = wid >> 1;       // 4 x 32 cols
    const int m0 = blockIdx.x * TILE_M;
    const uint32_t sbase = smem_to_u32(smem_f);

    // per-thread cp.async chunk plan (6 x 16B per stage)
    const char* srcs[CPT];
    uint32_t dsts[CPT];
    #pragma unroll
    for (int u = 0; u < CPT; u++) {
        int id = tid + u * 256;
        if (id < CHUNKS_A) {
            int row = id >> 3, c = id & 7;
            dsts[u] = (uint32_t)(row * (ROWPAD * 4) + c * 16);
            srcs[u] = (const char*)(A + (size_t)(m0 + row) * N_NODES) + c * 16;
        } else {
            int b = id - CHUNKS_A;
            int row = b >> 3, c = b & 7;
            dsts[u] = A_STAGE_B + (uint32_t)(row * (ROWPAD * 4) + c * 16);
            srcs[u] = (const char*)(g_Gt + (size_t)row * N_NODES) + c * 16;
        }
    }

    auto issue = [&](int j) {
        const uint32_t st = sbase + (uint32_t)(j % STAGES) * STAGE_B;
        const size_t koff = (size_t)j * (KC * 4);
        #pragma unroll
        for (int u = 0; u < CPT; u++) {
            asm volatile("cp.async.cg.shared.global [%0], [%1], 16;"
                         :: "r"(st + dsts[u]), "l"(srcs[u] + koff) : "memory");
        }
    };

    // prologue: fill 5 stages
    #pragma unroll
    for (int p = 0; p < STAGES - 1; p++) {
        issue(p);
        asm volatile("cp.async.commit_group;" ::: "memory");
    }

    const int qr = lane >> 2;          // 0..7
    const int qc = lane & 3;           // 0..3
    const int a_base = (warp_m * 32 + qr) * ROWPAD + qc;
    const int b_base = (warp_n * 32 + qr) * ROWPAD + qc;

    float acc[2][4][4];
    #pragma unroll
    for (int mf = 0; mf < 2; mf++)
        #pragma unroll
        for (int nf = 0; nf < 4; nf++)
            #pragma unroll
            for (int q = 0; q < 4; q++) acc[mf][nf][q] = 0.f;

    for (int i = 0; i < ITERS; i++) {
        asm volatile("cp.async.wait_group %0;" :: "n"(STAGES - 2) : "memory");
        __syncthreads();
        if (i + STAGES - 1 < ITERS) issue(i + STAGES - 1);
        asm volatile("cp.async.commit_group;" ::: "memory");

        const float* Sf = smem_f + (i % STAGES) * STAGE_F;
        const float* Bf = Sf + A_STAGE_F;
        #pragma unroll
        for (int k8 = 0; k8 < 4; k8++) {
            const int co = k8 * 8;
            uint32_t afr[2][4], bfr[4][2];
            #pragma unroll
            for (int mf = 0; mf < 2; mf++) {
                const int ab = a_base + mf * (16 * ROWPAD) + co;
                afr[mf][0] = __float_as_uint(Sf[ab]);
                afr[mf][1] = __float_as_uint(Sf[ab + 8 * ROWPAD]);
                afr[mf][2] = __float_as_uint(Sf[ab + 4]);
                afr[mf][3] = __float_as_uint(Sf[ab + 8 * ROWPAD + 4]);
            }
            #pragma unroll
            for (int nf = 0; nf < 4; nf++) {
                const int bb = b_base + nf * (8 * ROWPAD) + co;
                bfr[nf][0] = __float_as_uint(Bf[bb]);
                bfr[nf][1] = __float_as_uint(Bf[bb + 4]);
            }
            #pragma unroll
            for (int mf = 0; mf < 2; mf++)
                #pragma unroll
                for (int nf = 0; nf < 4; nf++)
                    mma_tf32(acc[mf][nf], afr[mf], bfr[nf]);
        }
    }

    // fused epilogue: dinv_m scale + relu, straight to d_out
    #pragma unroll
    for (int mf = 0; mf < 2; mf++) {
        const int m = m0 + warp_m * 32 + mf * 16 + qr;
        const float d0 = g_dinv[m];
        const float d1 = g_dinv[m + 8];
        #pragma unroll
        for (int nf = 0; nf < 4; nf++) {
            const int n = warp_n * 32 + nf * 8 + 2 * qc;
            float2 v0, v1;
            v0.x = fmaxf(d0 * acc[mf][nf][0], 0.f);
            v0.y = fmaxf(d0 * acc[mf][nf][1], 0.f);
            v1.x = fmaxf(d1 * acc[mf][nf][2], 0.f);
            v1.y = fmaxf(d1 * acc[mf][nf][3], 0.f);
            *reinterpret_cast<float2*>(out + (size_t)m * D_FEAT + n) = v0;
            *reinterpret_cast<float2*>(out + (size_t)(m + 8) * D_FEAT + n) = v1;
        }
    }
}

// ============================================================================
// Launch
// ============================================================================

extern "C" void kernel_launch(void* const* d_in, const int* in_sizes, int n_in,
                              void* d_out, int out_size) {
    const float* A = (const float*)d_in[0];
    const float* X = (const float*)d_in[1];
    const float* W = (const float*)d_in[2];
    for (int i = 0; i < n_in; i++) {
        if (in_sizes[i] == N_NODES * N_NODES)      A = (const float*)d_in[i];
        else if (in_sizes[i] == N_NODES * D_FEAT)  X = (const float*)d_in[i];
        else if (in_sizes[i] == D_FEAT * D_FEAT)   W = (const float*)d_in[i];
    }
    float* out = (float*)d_out;

    cudaFuncSetAttribute(build_gt, cudaFuncAttributeMaxDynamicSharedMemorySize,
                         K2_SMEM);
    cudaFuncSetAttribute(gcn_gemm, cudaFuncAttributeMaxDynamicSharedMemorySize,
                         GEMM_SMEM);

    deg_kernel<<<N_NODES, 128>>>(A);
    build_gt<<<N_NODES / K2_ROWS, 128, K2_SMEM>>>(X, W);
    gcn_gemm<<<N_NODES / TILE_M, 256, GEMM_SMEM>>>(A, out);
}

// round 7
// speedup vs baseline: 1.1860x; 1.1860x over previous
#include <cuda_runtime.h>
#include <cuda_fp16.h>
#include <cstdint>
#include <cstddef>

// ============================================================================
// GCN layer: out = relu(dinv_m * (A @ (dinv_k * (X W^T)))), A 8192x8192 fp32.
// PTX target is plain sm_100 (no tcgen05) -> mma.sync.m16n8k16.f16 (10-bit
// mantissa like tf32, fp32 accumulate, half the MMA instructions of tf32).
// A is converted fp32->fp16 INLINE in the GEMM load path (no 128 MB scratch).
// ============================================================================

static constexpr int N_NODES = 8192;
static constexpr int D_FEAT  = 128;

__device__ __align__(128) float  g_dinv[N_NODES];
__device__ __align__(128) __half g_Gh[(size_t)D_FEAT * N_NODES];  // 2 MB, [o][k]

__device__ __forceinline__ uint32_t h2_as_u32(__half2 h) {
    return *reinterpret_cast<uint32_t*>(&h);
}

// ============================================================================
// K1: deg row sums -> dinv = rsqrt(deg). Pure 268 MB DRAM stream (R2: 42 us).
// ============================================================================

__global__ __launch_bounds__(128) void deg_kernel(const float* __restrict__ A) {
    __shared__ float red[4];
    const int row = blockIdx.x;
    const int t = threadIdx.x;
    const float4* a4 = reinterpret_cast<const float4*>(A + (size_t)row * N_NODES);
    float s0 = 0.f, s1 = 0.f, s2 = 0.f, s3 = 0.f;
    #pragma unroll
    for (int i = 0; i < 4; i++) {
        float4 v0 = a4[t + (4 * i + 0) * 128];
        float4 v1 = a4[t + (4 * i + 1) * 128];
        float4 v2 = a4[t + (4 * i + 2) * 128];
        float4 v3 = a4[t + (4 * i + 3) * 128];
        s0 += v0.x + v0.y + v0.z + v0.w;
        s1 += v1.x + v1.y + v1.z + v1.w;
        s2 += v2.x + v2.y + v2.z + v2.w;
        s3 += v3.x + v3.y + v3.z + v3.w;
    }
    float s = (s0 + s1) + (s2 + s3);
    #pragma unroll
    for (int off = 16; off > 0; off >>= 1)
        s += __shfl_xor_sync(0xFFFFFFFFu, s, off);
    if ((t & 31) == 0) red[t >> 5] = s;
    __syncthreads();
    if (t == 0) {
        float total = (red[0] + red[1]) + (red[2] + red[3]);
        g_dinv[row] = rsqrtf(total);
    }
}

// ============================================================================
// K2: Gh[o][k] = fp16( dinv[k] * sum_d X[k][d] * W[o][d] )
// ============================================================================

static constexpr int K2_ROWS = 32;
static constexpr int W_PAD   = 132;
static constexpr int K2_SMEM = (128 * W_PAD + 128) * 4;

__global__ __launch_bounds__(128) void build_gt(const float* __restrict__ X,
                                                const float* __restrict__ W) {
    extern __shared__ __align__(16) float k2sm[];
    float* Ws = k2sm;                 // [128][W_PAD]
    float* Xs = k2sm + 128 * W_PAD;   // [128]

    for (int idx = threadIdx.x; idx < 128 * 128; idx += 128) {
        int o = idx >> 7, d = idx & 127;
        Ws[o * W_PAD + d] = W[idx];
    }
    __syncthreads();

    const int k0 = blockIdx.x * K2_ROWS;
    const int o = threadIdx.x;
    const float4* Wrow = reinterpret_cast<const float4*>(Ws + o * W_PAD);

    for (int kk = 0; kk < K2_ROWS; kk++) {
        const int k = k0 + kk;
        Xs[o] = X[(size_t)k * 128 + o];
        __syncthreads();
        const float4* X4 = reinterpret_cast<const float4*>(Xs);
        float acc = 0.f;
        #pragma unroll
        for (int q = 0; q < 32; q++) {
            float4 w = Wrow[q];
            float4 x = X4[q];
            acc += w.x * x.x + w.y * x.y + w.z * x.z + w.w * x.w;
        }
        g_Gh[(size_t)o * N_NODES + k] = __float2half_rn(acc * g_dinv[k]);
        __syncthreads();
    }
}

// ============================================================================
// K3: fp16 mma.sync GEMM + fused epilogue.
//   out[m][o] = relu(dinv[m] * sum_k fp16(A[m][k]) * Gh[o][k])
// CTA tile 64x128, KC=64, 4-stage smem ring. A: LDG fp32 -> cvt -> STS fp16
// with 2-stage register prefetch. B: cp.async (g_Gh is L2-resident).
// 512 threads (16 warps, warp tile 32x16), ldmatrix.x4 fragment loads.
// Rows padded to 72 halves (144 B): all ldmatrix/STS phases conflict-free.
// ============================================================================

static constexpr int TILE_M = 64;
static constexpr int TILE_N = 128;
static constexpr int KC     = 64;
static constexpr int STAGES = 4;
static constexpr int ITERS  = N_NODES / KC;                    // 128
static constexpr int ROWF   = 72;
static constexpr int ROWB   = ROWF * 2;                        // 144 B
static constexpr uint32_t A_STAGE_B = TILE_M * ROWB;           // 9216
static constexpr uint32_t B_STAGE_B = TILE_N * ROWB;           // 18432
static constexpr uint32_t STAGE_B   = A_STAGE_B + B_STAGE_B;   // 27648
static constexpr uint32_t GEMM_SMEM = STAGES * STAGE_B;        // 110592
static constexpr int NTHR    = 512;
static constexpr int B_CHUNKS = TILE_N * (KC * 2 / 16);        // 1024
static constexpr int B_CPT    = B_CHUNKS / NTHR;               // 2

__device__ __forceinline__ uint32_t smem_to_u32(const void* p) {
    uint32_t a;
    asm("{ .reg .u64 t; cvta.to.shared.u64 t, %1; cvt.u32.u64 %0, t; }"
        : "=r"(a) : "l"(p));
    return a;
}

__device__ __forceinline__ void ldsm_x4(uint32_t r[4], uint32_t addr) {
    asm volatile("ldmatrix.sync.aligned.m8n8.x4.shared.b16 {%0,%1,%2,%3}, [%4];"
                 : "=r"(r[0]), "=r"(r[1]), "=r"(r[2]), "=r"(r[3]) : "r"(addr));
}

__device__ __forceinline__ void mma_f16(float d[4], const uint32_t a[4],
                                        uint32_t b0, uint32_t b1) {
    asm volatile(
        "mma.sync.aligned.m16n8k16.row.col.f32.f16.f16.f32 "
        "{%0,%1,%2,%3}, {%4,%5,%6,%7}, {%8,%9}, {%0,%1,%2,%3};"
        : "+f"(d[0]), "+f"(d[1]), "+f"(d[2]), "+f"(d[3])
        : "r"(a[0]), "r"(a[1]), "r"(a[2]), "r"(a[3]), "r"(b0), "r"(b1));
}

__global__ __launch_bounds__(NTHR, 1) void gcn_gemm(const float* __restrict__ A,
                                                    float* __restrict__ out) {
    extern __shared__ __align__(16) char smem_c[];
    const int tid = threadIdx.x;
    const int lane = tid & 31;
    const int wid = tid >> 5;
    const int warp_m = wid & 1;        // 2 warp rows of 32
    const int warp_n = wid >> 1;       // 8 warp cols of 16
    const int m0 = blockIdx.x * TILE_M;
    const uint32_t sbase = smem_to_u32(smem_c);

    // ---- A load plan: thread -> (row = tid/8, seg = tid%8), 8 floats each
    const int a_row = tid >> 3;
    const int a_seg = tid & 7;
    const float4* a_src = reinterpret_cast<const float4*>(
        A + (size_t)(m0 + a_row) * N_NODES + a_seg * 8);
    const uint32_t a_sts = sbase + (uint32_t)(a_row * ROWB + a_seg * 16);

    // ---- B cp.async plan: 2 x 16B per thread per stage
    const char* b_srcs[B_CPT];
    uint32_t b_dsts[B_CPT];
    #pragma unroll
    for (int u = 0; u < B_CPT; u++) {
        int id = tid + u * NTHR;
        int row = id >> 3, c = id & 7;
        b_dsts[u] = A_STAGE_B + (uint32_t)(row * ROWB + c * 16);
        b_srcs[u] = (const char*)(g_Gh + (size_t)row * N_NODES) + c * 16;
    }

    auto issueB = [&](int j) {
        const uint32_t st = sbase + (uint32_t)(j % STAGES) * STAGE_B;
        const size_t koff = (size_t)j * (KC * 2);
        #pragma unroll
        for (int u = 0; u < B_CPT; u++) {
            asm volatile("cp.async.cg.shared.global [%0], [%1], 16;"
                         :: "r"(st + b_dsts[u]), "l"(b_srcs[u] + koff) : "memory");
        }
    };
    auto ldgA = [&](int j, float4 r[2]) {
        const float4* p = a_src + (size_t)j * 16;   // 16 float4 per row-chunk
        r[0] = p[0];
        r[1] = p[1];
    };
    auto stsA = [&](int j, const float4 r[2]) {
        uint32_t h0 = h2_as_u32(__floats2half2_rn(r[0].x, r[0].y));
        uint32_t h1 = h2_as_u32(__floats2half2_rn(r[0].z, r[0].w));
        uint32_t h2 = h2_as_u32(__floats2half2_rn(r[1].x, r[1].y));
        uint32_t h3 = h2_as_u32(__floats2half2_rn(r[1].z, r[1].w));
        const uint32_t ad = a_sts + (uint32_t)(j % STAGES) * STAGE_B;
        asm volatile("st.shared.v4.b32 [%0], {%1,%2,%3,%4};"
                     :: "r"(ad), "r"(h0), "r"(h1), "r"(h2), "r"(h3) : "memory");
    };

    // ---- prologue
    float4 regA[2][2];
    ldgA(0, regA[0]);
    ldgA(1, regA[1]);
    issueB(0); asm volatile("cp.async.commit_group;" ::: "memory");
    issueB(1); asm volatile("cp.async.commit_group;" ::: "memory");
    issueB(2); asm volatile("cp.async.commit_group;" ::: "memory");
    stsA(0, regA[0]);

    // ---- ldmatrix lane addressing (bytes, within stage)
    const uint32_t a_off = (uint32_t)((warp_m * 32 + (lane & 15)) * ROWB
                                      + ((lane >> 4) * 8) * 2);
    const uint32_t b_off = A_STAGE_B
        + (uint32_t)((warp_n * 16 + ((lane >> 4) << 3) + (lane & 7)) * ROWB
                     + (((lane >> 3) & 1) * 8) * 2);

    float acc[2][2][4];
    #pragma unroll
    for (int mf = 0; mf < 2; mf++)
        #pragma unroll
        for (int nf = 0; nf < 2; nf++)
            #pragma unroll
            for (int q = 0; q < 4; q++) acc[mf][nf][q] = 0.f;

    for (int i = 0; i < ITERS; i++) {
        asm volatile("cp.async.wait_group %0;" :: "n"(STAGES - 2) : "memory");
        __syncthreads();   // B(i) arrived; A(i) STS visible

        if (i + 2 < ITERS) ldgA(i + 2, regA[i & 1]);
        if (i + 3 < ITERS) issueB(i + 3);
        asm volatile("cp.async.commit_group;" ::: "memory");
        if (i + 1 < ITERS) stsA(i + 1, regA[(i + 1) & 1]);

        const uint32_t st = sbase + (uint32_t)(i % STAGES) * STAGE_B;
        const uint32_t aA = st + a_off;
        const uint32_t aB = st + b_off;
        #pragma unroll
        for (int kk = 0; kk < KC / 16; kk++) {
            const uint32_t ko = (uint32_t)(kk * 32);   // 16 halves = 32 B
            uint32_t af0[4], af1[4], bf[4];
            ldsm_x4(af0, aA + ko);
            ldsm_x4(af1, aA + 16 * ROWB + ko);
            ldsm_x4(bf, aB + ko);
            mma_f16(acc[0][0], af0, bf[0], bf[1]);
            mma_f16(acc[0][1], af0, bf[2], bf[3]);
            mma_f16(acc[1][0], af1, bf[0], bf[1]);
            mma_f16(acc[1][1], af1, bf[2], bf[3]);
        }
    }

    // ---- fused epilogue: dinv_m scale + relu -> d_out
    const int qr = lane >> 2;
    const int qc = lane & 3;
    #pragma unroll
    for (int mf = 0; mf < 2; mf++) {
        const int m = m0 + warp_m * 32 + mf * 16 + qr;
        const float d0 = g_dinv[m];
        const float d1 = g_dinv[m + 8];
        #pragma unroll
        for (int nf = 0; nf < 2; nf++) {
            const int n = warp_n * 16 + nf * 8 + 2 * qc;
            float2 v0, v1;
            v0.x = fmaxf(d0 * acc[mf][nf][0], 0.f);
            v0.y = fmaxf(d0 * acc[mf][nf][1], 0.f);
            v1.x = fmaxf(d1 * acc[mf][nf][2], 0.f);
            v1.y = fmaxf(d1 * acc[mf][nf][3], 0.f);
            *reinterpret_cast<float2*>(out + (size_t)m * D_FEAT + n) = v0;
            *reinterpret_cast<float2*>(out + (size_t)(m + 8) * D_FEAT + n) = v1;
        }
    }
}

// ============================================================================
// Launch
// ============================================================================

extern "C" void kernel_launch(void* const* d_in, const int* in_sizes, int n_in,
                              void* d_out, int out_size) {
    const float* A = (const float*)d_in[0];
    const float* X = (const float*)d_in[1];
    const float* W = (const float*)d_in[2];
    for (int i = 0; i < n_in; i++) {
        if (in_sizes[i] == N_NODES * N_NODES)      A = (const float*)d_in[i];
        else if (in_sizes[i] == N_NODES * D_FEAT)  X = (const float*)d_in[i];
        else if (in_sizes[i] == D_FEAT * D_FEAT)   W = (const float*)d_in[i];
    }
    float* out = (float*)d_out;

    cudaFuncSetAttribute(build_gt, cudaFuncAttributeMaxDynamicSharedMemorySize,
                         K2_SMEM);
    cudaFuncSetAttribute(gcn_gemm, cudaFuncAttributeMaxDynamicSharedMemorySize,
                         GEMM_SMEM);

    deg_kernel<<<N_NODES, 128>>>(A);
    build_gt<<<N_NODES / K2_ROWS, 128, K2_SMEM>>>(X, W);
    gcn_gemm<<<N_NODES / TILE_M, NTHR, GEMM_SMEM>>>(A, out);
}